// round 2
// baseline (speedup 1.0000x reference)
#include <cuda_runtime.h>
#include <cuda_bf16.h>

// Problem constants (fixed shapes for this dataset)
#define BATCH   16
#define FDIM    128
#define NMAX    10000
#define EMAX    320000
#define H1DIM   16
#define H2DIM   32
#define NCLS    10
#define BK      (BATCH * H2DIM)   // 512

// ---------------- device scratch (no allocations allowed) ----------------
__device__ float g_dis[NMAX];          // deg -> dis (rsqrt)
__device__ float g_self[NMAX];         // dis*dis
__device__ int   g_cnt[NMAX];          // in-degree histogram
__device__ int   g_off[NMAX + 1];      // CSR offsets
__device__ int   g_cur[NMAX];          // fill cursors
__device__ int   g_crow[EMAX];         // CSR source node per edge
__device__ float g_cnorm[EMAX];        // CSR norm per edge
__device__ float g_h[NMAX * BATCH];           // encoder out, layout [n][b]
__device__ float g_xp2[NMAX * BK];            // layer2 input, layout [n][b*32+k]  (20.5 MB)
__device__ float g_pool[BK];                  // pooled sums

// ---------------- K0: init ----------------
__global__ void k_init(int N) {
    int i = blockIdx.x * blockDim.x + threadIdx.x;
    if (i < N) {
        g_dis[i] = 1.0f;   // deg starts at 1 (self loop)
        g_cnt[i] = 0;
    }
    if (i < BK) g_pool[i] = 0.0f;
}

// ---------------- K1: degree + histogram ----------------
__global__ void k_deg(const int* __restrict__ ei, const float* __restrict__ ew, int E) {
    int e = blockIdx.x * blockDim.x + threadIdx.x;
    if (e >= E) return;
    int c = ei[E + e];
    atomicAdd(&g_dis[c], ew[e]);
    atomicAdd(&g_cnt[c], 1);
}

// ---------------- K2: dis = rsqrt(deg), self = dis^2 ----------------
__global__ void k_dis(int N) {
    int i = blockIdx.x * blockDim.x + threadIdx.x;
    if (i >= N) return;
    float d = rsqrtf(g_dis[i]);
    g_dis[i] = d;
    g_self[i] = d * d;
}

// ---------------- K3: exclusive scan of cnt -> off, cur (single block) ----------------
__global__ void k_scan(int N) {
    __shared__ int sh[1024];
    int tid = threadIdx.x;
    int carry = 0;
    for (int base = 0; base < N; base += 1024) {
        int i = base + tid;
        int v = (i < N) ? g_cnt[i] : 0;
        sh[tid] = v;
        __syncthreads();
        #pragma unroll
        for (int off = 1; off < 1024; off <<= 1) {
            int t = (tid >= off) ? sh[tid - off] : 0;
            __syncthreads();
            sh[tid] += t;
            __syncthreads();
        }
        int incl = sh[tid];
        if (i < N) {
            int ex = carry + incl - v;
            g_off[i] = ex;
            g_cur[i] = ex;
        }
        int tot = sh[1023];
        __syncthreads();
        carry += tot;
    }
    if (tid == 0) g_off[N] = carry;
}

// ---------------- K4: CSR fill ----------------
__global__ void k_fill(const int* __restrict__ ei, const float* __restrict__ ew, int E) {
    int e = blockIdx.x * blockDim.x + threadIdx.x;
    if (e >= E) return;
    int r = ei[e];
    int c = ei[E + e];
    int p = atomicAdd(&g_cur[c], 1);
    g_crow[p] = r;
    g_cnorm[p] = g_dis[r] * ew[e] * g_dis[c];
}

// ---------------- K5: encoder  h[n][b] = x[b,:]·enc_W[:,n] + enc_b[n] ----------------
__global__ void k_enc(const float* __restrict__ x, const float* __restrict__ encW,
                      const float* __restrict__ encb, int N) {
    __shared__ float sx[BATCH * FDIM];
    int tid = threadIdx.x;
    for (int i = tid; i < BATCH * FDIM; i += blockDim.x) sx[i] = x[i];
    __syncthreads();
    int n = blockIdx.x * blockDim.x + tid;
    if (n >= N) return;
    float acc[BATCH];
    #pragma unroll
    for (int b = 0; b < BATCH; b++) acc[b] = 0.0f;
    for (int f = 0; f < FDIM; f++) {
        float w = encW[(size_t)f * N + n];
        #pragma unroll
        for (int b = 0; b < BATCH; b++) acc[b] = fmaf(sx[b * FDIM + f], w, acc[b]);
    }
    float eb = encb[n];
    #pragma unroll
    for (int b = 0; b < BATCH; b++) g_h[n * BATCH + b] = acc[b] + eb;
}

// ---------------- K6: layer1 scalar aggregation + expand + GEMM -> xp2 ----------------
// block = 256 threads = 16 nodes x 16 batch
__global__ void k_l1(const float* __restrict__ W1, const float* __restrict__ b1,
                     const float* __restrict__ W2, int N) {
    __shared__ float sW1[H1DIM], sb1[H1DIM], sW2[H1DIM * H2DIM];
    int tid = threadIdx.x;
    if (tid < H1DIM) { sW1[tid] = W1[tid]; sb1[tid] = b1[tid]; }
    for (int i = tid; i < H1DIM * H2DIM; i += blockDim.x) sW2[i] = W2[i];
    __syncthreads();

    int c = blockIdx.x * 16 + (tid >> 4);
    int b = tid & 15;
    if (c >= N) return;

    float agg = g_self[c] * g_h[c * BATCH + b];
    int s = g_off[c], e = g_off[c + 1];
    #pragma unroll 4
    for (int p = s; p < e; p++)
        agg = fmaf(g_cnorm[p], g_h[g_crow[p] * BATCH + b], agg);

    float acc[H2DIM];
    #pragma unroll
    for (int k = 0; k < H2DIM; k++) acc[k] = 0.0f;
    #pragma unroll
    for (int j = 0; j < H1DIM; j++) {
        float h1 = fmaxf(fmaf(agg, sW1[j], sb1[j]), 0.0f);
        #pragma unroll
        for (int k = 0; k < H2DIM; k++) acc[k] = fmaf(h1, sW2[j * H2DIM + k], acc[k]);
    }
    float4* dst = (float4*)&g_xp2[((size_t)c * BATCH + b) * H2DIM];
    #pragma unroll
    for (int k4 = 0; k4 < H2DIM / 4; k4++)
        dst[k4] = make_float4(acc[k4 * 4], acc[k4 * 4 + 1], acc[k4 * 4 + 2], acc[k4 * 4 + 3]);
}

// ---------------- K7: layer2 aggregation + relu + pooling ----------------
// block = 512 threads = (b,k); NPB nodes per block; edges staged via shared mem
#define NPB 8
#define CH  512
__global__ void k_l2(const float* __restrict__ b2, int N) {
    __shared__ int   s_row[CH];
    __shared__ float s_norm[CH];
    int tid = threadIdx.x;                 // = b*32 + k
    float bk = b2[tid & 31];
    float psum = 0.0f;

    int c0 = blockIdx.x * NPB;
    for (int i = 0; i < NPB; i++) {
        int c = c0 + i;
        if (c >= N) break;                  // uniform across block
        int s = g_off[c], e = g_off[c + 1];
        float acc = g_self[c] * g_xp2[(size_t)c * BK + tid];
        for (int base = s; base < e; base += CH) {
            int m = min(CH, e - base);
            if (tid < m) {
                s_row[tid] = g_crow[base + tid];
                s_norm[tid] = g_cnorm[base + tid];
            }
            __syncthreads();
            float a0 = 0.f, a1 = 0.f, a2 = 0.f, a3 = 0.f;
            int p = 0;
            for (; p + 4 <= m; p += 4) {
                a0 = fmaf(s_norm[p],     g_xp2[(size_t)s_row[p]     * BK + tid], a0);
                a1 = fmaf(s_norm[p + 1], g_xp2[(size_t)s_row[p + 1] * BK + tid], a1);
                a2 = fmaf(s_norm[p + 2], g_xp2[(size_t)s_row[p + 2] * BK + tid], a2);
                a3 = fmaf(s_norm[p + 3], g_xp2[(size_t)s_row[p + 3] * BK + tid], a3);
            }
            for (; p < m; p++)
                a0 = fmaf(s_norm[p], g_xp2[(size_t)s_row[p] * BK + tid], a0);
            acc += (a0 + a1) + (a2 + a3);
            __syncthreads();
        }
        psum += fmaxf(acc + bk, 0.0f);
    }
    atomicAdd(&g_pool[tid], psum);
}

// ---------------- K8: classifier head ----------------
__global__ void k_head(const float* __restrict__ c1W, const float* __restrict__ c1b,
                       const float* __restrict__ c2W, const float* __restrict__ c2b,
                       float* __restrict__ out, int N) {
    __shared__ float sp[BK];
    __shared__ float sz[BATCH * H1DIM];
    int tid = threadIdx.x;                 // 256 threads
    float invN = 1.0f / (float)N;
    for (int i = tid; i < BK; i += 256) sp[i] = g_pool[i] * invN;   // FIX: full 512 load
    __syncthreads();
    {
        int b = tid >> 4, j = tid & 15;
        float acc = c1b[j];
        #pragma unroll
        for (int k = 0; k < H2DIM; k++) acc = fmaf(sp[b * H2DIM + k], c1W[k * H1DIM + j], acc);
        sz[b * H1DIM + j] = fmaxf(acc, 0.0f);
    }
    __syncthreads();
    if (tid < BATCH * NCLS) {
        int b = tid / NCLS, cc = tid % NCLS;
        float o = c2b[cc];
        #pragma unroll
        for (int j = 0; j < H1DIM; j++) o = fmaf(sz[b * H1DIM + j], c2W[j * NCLS + cc], o);
        out[tid] = o;
    }
}

// ---------------- launch ----------------
extern "C" void kernel_launch(void* const* d_in, const int* in_sizes, int n_in,
                              void* d_out, int out_size) {
    const float* x    = (const float*)d_in[0];
    const int*   ei   = (const int*)  d_in[1];
    const float* ew   = (const float*)d_in[2];
    const float* encW = (const float*)d_in[3];
    const float* encb = (const float*)d_in[4];
    const float* W1   = (const float*)d_in[5];
    const float* b1   = (const float*)d_in[6];
    const float* W2   = (const float*)d_in[7];
    const float* b2   = (const float*)d_in[8];
    const float* c1W  = (const float*)d_in[9];
    const float* c1b  = (const float*)d_in[10];
    const float* c2W  = (const float*)d_in[11];
    const float* c2b  = (const float*)d_in[12];
    float* out = (float*)d_out;

    int E = in_sizes[2];        // edge_weight count
    int N = in_sizes[4];        // enc_b count

    int nb256 = (N + 255) / 256;
    int eb256 = (E + 255) / 256;

    k_init<<<nb256, 256>>>(N);
    k_deg <<<eb256, 256>>>(ei, ew, E);
    k_dis <<<nb256, 256>>>(N);
    k_scan<<<1, 1024>>>(N);
    k_fill<<<eb256, 256>>>(ei, ew, E);
    k_enc <<<(N + 127) / 128, 128>>>(x, encW, encb, N);
    k_l1  <<<(N + 15) / 16, 256>>>(W1, b1, W2, N);
    k_l2  <<<(N + NPB - 1) / NPB, BK>>>(b2, N);
    k_head<<<1, 256>>>(c1W, c1b, c2W, c2b, out, N);
}

// round 3
// speedup vs baseline: 1.3211x; 1.3211x over previous
#include <cuda_runtime.h>
#include <cuda_bf16.h>

// Problem constants (fixed shapes for this dataset)
#define BATCH   16
#define FDIM    128
#define NMAX    10000
#define EMAX    320000
#define H1DIM   16
#define H2DIM   32
#define NCLS    10
#define BJ      (BATCH * H1DIM)   // 256  (layer-2 aggregation channels)
#define BK      (BATCH * H2DIM)   // 512  (pooled vector)

// ---------------- device scratch (no allocations allowed) ----------------
__device__ float g_dis[NMAX];          // deg -> dis (rsqrt)
__device__ float g_self[NMAX];         // dis*dis
__device__ int   g_cnt[NMAX];          // in-degree histogram
__device__ int   g_off[NMAX + 1];      // CSR offsets
__device__ int   g_cur[NMAX];          // fill cursors
__device__ int   g_crow[EMAX];         // CSR source node per edge
__device__ float g_cnorm[EMAX];        // CSR norm per edge
__device__ float g_h[NMAX * BATCH];    // encoder out, layout [n][b]
__device__ float g_h1[NMAX * BJ];      // relu(layer1 out), layout [n][b*16+j] (10.24 MB)
__device__ float g_pool[BK];           // pooled sums

// ---------------- K0: init ----------------
__global__ void k_init(int N) {
    int i = blockIdx.x * blockDim.x + threadIdx.x;
    if (i < N) {
        g_dis[i] = 1.0f;   // deg starts at 1 (self loop)
        g_cnt[i] = 0;
    }
    if (i < BK) g_pool[i] = 0.0f;
}

// ---------------- K1: degree + histogram ----------------
__global__ void k_deg(const int* __restrict__ ei, const float* __restrict__ ew, int E) {
    int e = blockIdx.x * blockDim.x + threadIdx.x;
    if (e >= E) return;
    int c = ei[E + e];
    atomicAdd(&g_dis[c], ew[e]);
    atomicAdd(&g_cnt[c], 1);
}

// ---------------- K2: dis = rsqrt(deg), self = dis^2 ----------------
__global__ void k_dis(int N) {
    int i = blockIdx.x * blockDim.x + threadIdx.x;
    if (i >= N) return;
    float d = rsqrtf(g_dis[i]);
    g_dis[i] = d;
    g_self[i] = d * d;
}

// ---------------- K3: raking exclusive scan (single block, single pass) ----------------
__global__ void k_scan(int N) {
    __shared__ int s_warp[32];
    int tid = threadIdx.x;                       // 1024 threads
    int lane = tid & 31, wid = tid >> 5;
    int chunk = (N + 1023) >> 10;
    int s = tid * chunk;
    int e = min(s + chunk, N);

    int sum = 0;
    for (int i = s; i < e; i++) sum += g_cnt[i];

    // warp-inclusive scan of per-thread sums
    int incl = sum;
    #pragma unroll
    for (int o = 1; o < 32; o <<= 1) {
        int t = __shfl_up_sync(0xffffffffu, incl, o);
        if (lane >= o) incl += t;
    }
    if (lane == 31) s_warp[wid] = incl;
    __syncthreads();
    if (wid == 0) {
        int v = s_warp[lane];
        int wi = v;
        #pragma unroll
        for (int o = 1; o < 32; o <<= 1) {
            int t = __shfl_up_sync(0xffffffffu, wi, o);
            if (lane >= o) wi += t;
        }
        s_warp[lane] = wi - v;                   // exclusive warp bases
    }
    __syncthreads();
    int ex = s_warp[wid] + incl - sum;           // exclusive prefix for this thread

    int run = ex;
    for (int i = s; i < e; i++) {
        g_off[i] = run;
        g_cur[i] = run;
        run += g_cnt[i];
    }
    if (tid == 1023) g_off[N] = run;             // total (run==ex==total if chunk empty)
}

// ---------------- K4: CSR fill ----------------
__global__ void k_fill(const int* __restrict__ ei, const float* __restrict__ ew, int E) {
    int e = blockIdx.x * blockDim.x + threadIdx.x;
    if (e >= E) return;
    int r = ei[e];
    int c = ei[E + e];
    int p = atomicAdd(&g_cur[c], 1);
    g_crow[p] = r;
    g_cnorm[p] = g_dis[r] * ew[e] * g_dis[c];
}

// ---------------- K5: encoder  h[n][b] = x[b,:]·enc_W[:,n] + enc_b[n] ----------------
__global__ void k_enc(const float* __restrict__ x, const float* __restrict__ encW,
                      const float* __restrict__ encb, int N) {
    __shared__ float sx[BATCH * FDIM];
    int tid = threadIdx.x;
    for (int i = tid; i < BATCH * FDIM; i += blockDim.x) sx[i] = x[i];
    __syncthreads();
    int n = blockIdx.x * blockDim.x + tid;
    if (n >= N) return;
    float acc[BATCH];
    #pragma unroll
    for (int b = 0; b < BATCH; b++) acc[b] = 0.0f;
    for (int f = 0; f < FDIM; f++) {
        float w = encW[(size_t)f * N + n];
        #pragma unroll
        for (int b = 0; b < BATCH; b++) acc[b] = fmaf(sx[b * FDIM + f], w, acc[b]);
    }
    float eb = encb[n];
    #pragma unroll
    for (int b = 0; b < BATCH; b++) g_h[n * BATCH + b] = acc[b] + eb;
}

// ---------------- K6: layer1 scalar aggregation + relu(h1) -> g_h1 ----------------
// block = 256 threads = 16 nodes x 16 batch
__global__ void k_l1(const float* __restrict__ W1, const float* __restrict__ b1, int N) {
    __shared__ float sW1[H1DIM], sb1[H1DIM];
    int tid = threadIdx.x;
    if (tid < H1DIM) { sW1[tid] = W1[tid]; sb1[tid] = b1[tid]; }
    __syncthreads();

    int c = blockIdx.x * 16 + (tid >> 4);
    int b = tid & 15;
    if (c >= N) return;

    float agg = g_self[c] * g_h[c * BATCH + b];
    int s = g_off[c], e = g_off[c + 1];
    #pragma unroll 4
    for (int p = s; p < e; p++)
        agg = fmaf(g_cnorm[p], g_h[g_crow[p] * BATCH + b], agg);

    float4* dst = (float4*)&g_h1[((size_t)c * BATCH + b) * H1DIM];
    #pragma unroll
    for (int j4 = 0; j4 < H1DIM / 4; j4++) {
        float4 v;
        v.x = fmaxf(fmaf(agg, sW1[j4 * 4 + 0], sb1[j4 * 4 + 0]), 0.0f);
        v.y = fmaxf(fmaf(agg, sW1[j4 * 4 + 1], sb1[j4 * 4 + 1]), 0.0f);
        v.z = fmaxf(fmaf(agg, sW1[j4 * 4 + 2], sb1[j4 * 4 + 2]), 0.0f);
        v.w = fmaxf(fmaf(agg, sW1[j4 * 4 + 3], sb1[j4 * 4 + 3]), 0.0f);
        dst[j4] = v;
    }
}

// ---------------- K7: layer2 aggregate relu(h1), then @W2 + relu + pool ----------------
// 256 threads = (b,j) channels; W2 applied post-aggregation (linearity).
#define NPB 8
#define CH  256
__global__ void k_l2(const float* __restrict__ W2, const float* __restrict__ b2, int N) {
    __shared__ int   s_row[CH];
    __shared__ float s_norm[CH];
    __shared__ float sagg[BJ];
    __shared__ float sW2[H1DIM * H2DIM];
    __shared__ float sb2[H2DIM];
    int tid = threadIdx.x;                 // = b*16 + j
    if (tid < H2DIM) sb2[tid] = b2[tid];
    for (int i = tid; i < H1DIM * H2DIM; i += CH) sW2[i] = W2[i];
    __syncthreads();

    int b  = tid >> 4;
    int k0 = tid & 15;                     // this thread produces outputs k0 and k0+16
    float ps0 = 0.0f, ps1 = 0.0f;

    int c0 = blockIdx.x * NPB;
    for (int i = 0; i < NPB; i++) {
        int c = c0 + i;
        if (c >= N) break;                  // uniform across block
        int s = g_off[c], e = g_off[c + 1];
        float acc = g_self[c] * g_h1[(size_t)c * BJ + tid];
        for (int base = s; base < e; base += CH) {
            int m = min(CH, e - base);
            if (tid < m) {
                s_row[tid]  = g_crow[base + tid];
                s_norm[tid] = g_cnorm[base + tid];
            }
            __syncthreads();
            float a0 = 0.f, a1 = 0.f, a2 = 0.f, a3 = 0.f;
            int p = 0;
            for (; p + 4 <= m; p += 4) {
                a0 = fmaf(s_norm[p],     g_h1[(size_t)s_row[p]     * BJ + tid], a0);
                a1 = fmaf(s_norm[p + 1], g_h1[(size_t)s_row[p + 1] * BJ + tid], a1);
                a2 = fmaf(s_norm[p + 2], g_h1[(size_t)s_row[p + 2] * BJ + tid], a2);
                a3 = fmaf(s_norm[p + 3], g_h1[(size_t)s_row[p + 3] * BJ + tid], a3);
            }
            for (; p < m; p++)
                a0 = fmaf(s_norm[p], g_h1[(size_t)s_row[p] * BJ + tid], a0);
            acc += (a0 + a1) + (a2 + a3);
            __syncthreads();
        }
        sagg[tid] = acc;
        __syncthreads();
        // v[b,k] = sum_j sagg[b*16+j] * W2[j*32+k] + b2[k]; relu; pool
        float v0 = sb2[k0], v1 = sb2[k0 + 16];
        #pragma unroll
        for (int j = 0; j < H1DIM; j++) {
            float a = sagg[b * H1DIM + j];
            v0 = fmaf(a, sW2[j * H2DIM + k0],      v0);
            v1 = fmaf(a, sW2[j * H2DIM + k0 + 16], v1);
        }
        ps0 += fmaxf(v0, 0.0f);
        ps1 += fmaxf(v1, 0.0f);
        __syncthreads();                    // sagg reused next node
    }
    atomicAdd(&g_pool[b * H2DIM + k0],      ps0);
    atomicAdd(&g_pool[b * H2DIM + k0 + 16], ps1);
}

// ---------------- K8: classifier head ----------------
__global__ void k_head(const float* __restrict__ c1W, const float* __restrict__ c1b,
                       const float* __restrict__ c2W, const float* __restrict__ c2b,
                       float* __restrict__ out, int N) {
    __shared__ float sp[BK];
    __shared__ float sz[BATCH * H1DIM];
    int tid = threadIdx.x;                 // 256 threads
    float invN = 1.0f / (float)N;
    for (int i = tid; i < BK; i += 256) sp[i] = g_pool[i] * invN;
    __syncthreads();
    {
        int b = tid >> 4, j = tid & 15;
        float acc = c1b[j];
        #pragma unroll
        for (int k = 0; k < H2DIM; k++) acc = fmaf(sp[b * H2DIM + k], c1W[k * H1DIM + j], acc);
        sz[b * H1DIM + j] = fmaxf(acc, 0.0f);
    }
    __syncthreads();
    if (tid < BATCH * NCLS) {
        int b = tid / NCLS, cc = tid % NCLS;
        float o = c2b[cc];
        #pragma unroll
        for (int j = 0; j < H1DIM; j++) o = fmaf(sz[b * H1DIM + j], c2W[j * NCLS + cc], o);
        out[tid] = o;
    }
}

// ---------------- launch ----------------
extern "C" void kernel_launch(void* const* d_in, const int* in_sizes, int n_in,
                              void* d_out, int out_size) {
    const float* x    = (const float*)d_in[0];
    const int*   ei   = (const int*)  d_in[1];
    const float* ew   = (const float*)d_in[2];
    const float* encW = (const float*)d_in[3];
    const float* encb = (const float*)d_in[4];
    const float* W1   = (const float*)d_in[5];
    const float* b1   = (const float*)d_in[6];
    const float* W2   = (const float*)d_in[7];
    const float* b2   = (const float*)d_in[8];
    const float* c1W  = (const float*)d_in[9];
    const float* c1b  = (const float*)d_in[10];
    const float* c2W  = (const float*)d_in[11];
    const float* c2b  = (const float*)d_in[12];
    float* out = (float*)d_out;

    int E = in_sizes[2];        // edge_weight count
    int N = in_sizes[4];        // enc_b count

    int nb256 = (N + 255) / 256;
    int eb256 = (E + 255) / 256;

    k_init<<<nb256, 256>>>(N);
    k_deg <<<eb256, 256>>>(ei, ew, E);
    k_dis <<<nb256, 256>>>(N);
    k_scan<<<1, 1024>>>(N);
    k_fill<<<eb256, 256>>>(ei, ew, E);
    k_enc <<<(N + 127) / 128, 128>>>(x, encW, encb, N);
    k_l1  <<<(N + 15) / 16, 256>>>(W1, b1, N);
    k_l2  <<<(N + NPB - 1) / NPB, CH>>>(W2, b2, N);
    k_head<<<1, 256>>>(c1W, c1b, c2W, c2b, out, N);
}

// round 4
// speedup vs baseline: 1.5024x; 1.1372x over previous
#include <cuda_runtime.h>
#include <cuda_bf16.h>

// Problem constants (fixed shapes for this dataset)
#define BATCH   16
#define FDIM    128
#define NMAX    10000
#define EMAX    320000
#define H1DIM   16
#define H2DIM   32
#define NCLS    10
#define BK      (BATCH * H2DIM)   // 512  (pooled vector)

// ---------------- device scratch (no allocations allowed) ----------------
__device__ float g_dis[NMAX];            // deg -> dis (rsqrt)
__device__ float g_self[NMAX];           // dis*dis
__device__ int   g_cnt[NMAX];            // in-degree histogram
__device__ int   g_off[NMAX + 4];        // CSR offsets (+pad for int4 tail)
__device__ int   g_cur[NMAX + 4];        // fill cursors (+pad)
__device__ int   g_crow[EMAX];           // CSR source node per edge
__device__ float g_cnorm[EMAX];          // CSR norm per edge
__device__ float g_h[NMAX * BATCH];      // encoder out, layout [n][b]
__device__ float g_agg1[NMAX * BATCH];   // layer1 scalar aggregation, layout [n][b] (640 KB)
__device__ float g_pool[BK];             // pooled sums

// ---------------- K0: init ----------------
__global__ void k_init(int N) {
    int i = blockIdx.x * blockDim.x + threadIdx.x;
    if (i < N) {
        g_dis[i] = 1.0f;   // deg starts at 1 (self loop)
        g_cnt[i] = 0;
    }
    if (i < BK) g_pool[i] = 0.0f;
}

// ---------------- K1: degree + histogram ----------------
__global__ void k_deg(const int* __restrict__ ei, const float* __restrict__ ew, int E) {
    int e = blockIdx.x * blockDim.x + threadIdx.x;
    if (e >= E) return;
    int c = ei[E + e];
    atomicAdd(&g_dis[c], ew[e]);
    atomicAdd(&g_cnt[c], 1);
}

// ---------------- K2: dis = rsqrt(deg), self = dis^2 ----------------
__global__ void k_dis(int N) {
    int i = blockIdx.x * blockDim.x + threadIdx.x;
    if (i >= N) return;
    float d = rsqrtf(g_dis[i]);
    g_dis[i] = d;
    g_self[i] = d * d;
}

// ---------------- K3: raking exclusive scan, int4-vectorized (single block) ----------------
__global__ void k_scan(int N) {
    __shared__ int s_warp[32];
    int tid = threadIdx.x;                       // 1024 threads
    int lane = tid & 31, wid = tid >> 5;
    int V = (N + 3) >> 2;                        // int4 count
    int CV = (V + 1023) >> 10;                   // int4 per thread
    int s4 = tid * CV, e4 = min(s4 + CV, V);
    const int4* cnt4 = (const int4*)g_cnt;

    int sum = 0;
    for (int i4 = s4; i4 < e4; i4++) {
        int base = i4 * 4;
        int4 v = cnt4[i4];
        sum += v.x;
        if (base + 1 < N) sum += v.y;
        if (base + 2 < N) sum += v.z;
        if (base + 3 < N) sum += v.w;
    }

    // warp-inclusive scan of per-thread sums
    int incl = sum;
    #pragma unroll
    for (int o = 1; o < 32; o <<= 1) {
        int t = __shfl_up_sync(0xffffffffu, incl, o);
        if (lane >= o) incl += t;
    }
    if (lane == 31) s_warp[wid] = incl;
    __syncthreads();
    if (wid == 0) {
        int v = s_warp[lane];
        int wi = v;
        #pragma unroll
        for (int o = 1; o < 32; o <<= 1) {
            int t = __shfl_up_sync(0xffffffffu, wi, o);
            if (lane >= o) wi += t;
        }
        s_warp[lane] = wi - v;                   // exclusive warp bases
    }
    __syncthreads();
    int ex = s_warp[wid] + incl - sum;           // exclusive prefix for this thread

    int run = ex;
    int4* off4 = (int4*)g_off;
    int4* cur4 = (int4*)g_cur;
    for (int i4 = s4; i4 < e4; i4++) {
        int base = i4 * 4;
        int4 v = cnt4[i4];
        int4 o;
        o.x = run; run += v.x;
        o.y = run; if (base + 1 < N) run += v.y;
        o.z = run; if (base + 2 < N) run += v.z;
        o.w = run; if (base + 3 < N) run += v.w;
        off4[i4] = o;
        cur4[i4] = o;
    }
    if (tid == 1023) g_off[N] = run;             // run == ex == total when chunk empty
}

// ---------------- K4: CSR fill ----------------
__global__ void k_fill(const int* __restrict__ ei, const float* __restrict__ ew, int E) {
    int e = blockIdx.x * blockDim.x + threadIdx.x;
    if (e >= E) return;
    int r = ei[e];
    int c = ei[E + e];
    int p = atomicAdd(&g_cur[c], 1);
    g_crow[p] = r;
    g_cnorm[p] = g_dis[r] * ew[e] * g_dis[c];
}

// ---------------- K5: encoder  h[n][b] = x[b,:]·enc_W[:,n] + enc_b[n] ----------------
__global__ void k_enc(const float* __restrict__ x, const float* __restrict__ encW,
                      const float* __restrict__ encb, int N) {
    __shared__ float sx[BATCH * FDIM];
    int tid = threadIdx.x;
    for (int i = tid; i < BATCH * FDIM; i += blockDim.x) sx[i] = x[i];
    __syncthreads();
    int n = blockIdx.x * blockDim.x + tid;
    if (n >= N) return;
    float acc[BATCH];
    #pragma unroll
    for (int b = 0; b < BATCH; b++) acc[b] = 0.0f;
    for (int f = 0; f < FDIM; f++) {
        float w = encW[(size_t)f * N + n];
        #pragma unroll
        for (int b = 0; b < BATCH; b++) acc[b] = fmaf(sx[b * FDIM + f], w, acc[b]);
    }
    float eb = encb[n];
    #pragma unroll
    for (int b = 0; b < BATCH; b++) g_h[n * BATCH + b] = acc[b] + eb;
}

// ---------------- K6: layer1 scalar aggregation -> g_agg1 ----------------
// block = 256 threads = 16 nodes x 16 batch
__global__ void k_l1(int N) {
    int tid = threadIdx.x;
    int c = blockIdx.x * 16 + (tid >> 4);
    int b = tid & 15;
    if (c >= N) return;

    float agg = g_self[c] * g_h[c * BATCH + b];
    int s = g_off[c], e = g_off[c + 1];
    #pragma unroll 4
    for (int p = s; p < e; p++)
        agg = fmaf(g_cnorm[p], g_h[g_crow[p] * BATCH + b], agg);

    g_agg1[c * BATCH + b] = agg;
}

// ---------------- K7: layer2 — gather scalar agg1, expand via W1/relu inline,
// aggregate, then @W2 + b2 + relu + pool.  256 threads = (b,j). ----------------
#define NPB 8
#define CH2 64
__global__ void k_l2(const float* __restrict__ W1, const float* __restrict__ b1,
                     const float* __restrict__ W2, const float* __restrict__ b2, int N) {
    __shared__ float s_a[CH2 * 16];        // staged agg1 rows of sources
    __shared__ float s_norm[CH2];
    __shared__ float sagg[256];            // aggregated h1 for one node
    __shared__ float sW2[H1DIM * H2DIM];
    __shared__ float sb2[H2DIM];
    int tid = threadIdx.x;                 // = b*16 + j
    int b = tid >> 4, j = tid & 15;
    float w1 = W1[j];
    float bb1 = b1[j];
    if (tid < H2DIM) sb2[tid] = b2[tid];
    for (int i = tid; i < H1DIM * H2DIM; i += 256) sW2[i] = W2[i];
    __syncthreads();

    float ps0 = 0.0f, ps1 = 0.0f;
    int c0 = blockIdx.x * NPB;
    for (int i = 0; i < NPB; i++) {
        int c = c0 + i;
        if (c >= N) break;                  // uniform across block
        int s = g_off[c], e = g_off[c + 1];
        float acc = g_self[c] * fmaxf(fmaf(g_agg1[c * BATCH + b], w1, bb1), 0.0f);
        for (int base = s; base < e; base += CH2) {
            int m = min(CH2, e - base);
            if (tid < m) s_norm[tid] = g_cnorm[base + tid];
            {
                int f = tid & 15, ei = tid >> 4;   // 16 edges per pass, 4 passes
                #pragma unroll
                for (int pass = 0; pass < 4; pass++) {
                    int ep = ei + pass * 16;
                    if (ep < m) {
                        int r = g_crow[base + ep];           // broadcast within group
                        s_a[ep * 16 + f] = g_agg1[r * BATCH + f];  // 64B coalesced
                    }
                }
            }
            __syncthreads();
            float a0 = 0.f, a1 = 0.f, a2 = 0.f, a3 = 0.f;
            int p = 0;
            for (; p + 4 <= m; p += 4) {
                a0 = fmaf(s_norm[p],     fmaxf(fmaf(s_a[(p)     * 16 + b], w1, bb1), 0.f), a0);
                a1 = fmaf(s_norm[p + 1], fmaxf(fmaf(s_a[(p + 1) * 16 + b], w1, bb1), 0.f), a1);
                a2 = fmaf(s_norm[p + 2], fmaxf(fmaf(s_a[(p + 2) * 16 + b], w1, bb1), 0.f), a2);
                a3 = fmaf(s_norm[p + 3], fmaxf(fmaf(s_a[(p + 3) * 16 + b], w1, bb1), 0.f), a3);
            }
            for (; p < m; p++)
                a0 = fmaf(s_norm[p], fmaxf(fmaf(s_a[p * 16 + b], w1, bb1), 0.f), a0);
            acc += (a0 + a1) + (a2 + a3);
            __syncthreads();
        }
        sagg[tid] = acc;
        __syncthreads();
        // v[b,k] = sum_j sagg[b*16+j] * W2[j*32+k] + b2[k]; relu; pool
        float v0 = sb2[j], v1 = sb2[j + 16];
        #pragma unroll
        for (int jj = 0; jj < H1DIM; jj++) {
            float a = sagg[b * H1DIM + jj];
            v0 = fmaf(a, sW2[jj * H2DIM + j],      v0);
            v1 = fmaf(a, sW2[jj * H2DIM + j + 16], v1);
        }
        ps0 += fmaxf(v0, 0.0f);
        ps1 += fmaxf(v1, 0.0f);
        __syncthreads();                    // sagg reused next node
    }
    atomicAdd(&g_pool[b * H2DIM + j],      ps0);
    atomicAdd(&g_pool[b * H2DIM + j + 16], ps1);
}

// ---------------- K8: classifier head ----------------
__global__ void k_head(const float* __restrict__ c1W, const float* __restrict__ c1b,
                       const float* __restrict__ c2W, const float* __restrict__ c2b,
                       float* __restrict__ out, int N) {
    __shared__ float sp[BK];
    __shared__ float sz[BATCH * H1DIM];
    int tid = threadIdx.x;                 // 256 threads
    float invN = 1.0f / (float)N;
    for (int i = tid; i < BK; i += 256) sp[i] = g_pool[i] * invN;
    __syncthreads();
    {
        int b = tid >> 4, j = tid & 15;
        float acc = c1b[j];
        #pragma unroll
        for (int k = 0; k < H2DIM; k++) acc = fmaf(sp[b * H2DIM + k], c1W[k * H1DIM + j], acc);
        sz[b * H1DIM + j] = fmaxf(acc, 0.0f);
    }
    __syncthreads();
    if (tid < BATCH * NCLS) {
        int b = tid / NCLS, cc = tid % NCLS;
        float o = c2b[cc];
        #pragma unroll
        for (int j = 0; j < H1DIM; j++) o = fmaf(sz[b * H1DIM + j], c2W[j * NCLS + cc], o);
        out[tid] = o;
    }
}

// ---------------- launch ----------------
extern "C" void kernel_launch(void* const* d_in, const int* in_sizes, int n_in,
                              void* d_out, int out_size) {
    const float* x    = (const float*)d_in[0];
    const int*   ei   = (const int*)  d_in[1];
    const float* ew   = (const float*)d_in[2];
    const float* encW = (const float*)d_in[3];
    const float* encb = (const float*)d_in[4];
    const float* W1   = (const float*)d_in[5];
    const float* b1   = (const float*)d_in[6];
    const float* W2   = (const float*)d_in[7];
    const float* b2   = (const float*)d_in[8];
    const float* c1W  = (const float*)d_in[9];
    const float* c1b  = (const float*)d_in[10];
    const float* c2W  = (const float*)d_in[11];
    const float* c2b  = (const float*)d_in[12];
    float* out = (float*)d_out;

    int E = in_sizes[2];        // edge_weight count
    int N = in_sizes[4];        // enc_b count

    int nb256 = (N + 255) / 256;
    int eb256 = (E + 255) / 256;

    k_init<<<nb256, 256>>>(N);
    k_deg <<<eb256, 256>>>(ei, ew, E);
    k_dis <<<nb256, 256>>>(N);
    k_scan<<<1, 1024>>>(N);
    k_fill<<<eb256, 256>>>(ei, ew, E);
    k_enc <<<(N + 127) / 128, 128>>>(x, encW, encb, N);
    k_l1  <<<(N + 15) / 16, 256>>>(N);
    k_l2  <<<(N + NPB - 1) / NPB, 256>>>(W1, b1, W2, b2, N);
    k_head<<<1, 256>>>(c1W, c1b, c2W, c2b, out, N);
}